// round 2
// baseline (speedup 1.0000x reference)
#include <cuda_runtime.h>
#include <cuda_bf16.h>

// Problem constants
#define BATCH 16
#define NPTS 2048          // N == M == 2048
#define NUM_CLASSES 40
#define THREADS 256
#define CHUNKS 4           // N-chunks per (dir, batch); 512 points per block
#define NBLOCKS (2 * BATCH * CHUNKS)   // 128

// Deterministic scratch for per-block partial sums (no device alloc allowed)
__device__ float g_partials[NBLOCKS];

// One block: one (direction, batch, chunk-of-512-query-points).
// Loads the full target cloud (2048 pts) into SMEM as float4 (xyz, |y|^2),
// each thread owns 2 query points and scans all 2048 targets.
// d(x,y) = |x|^2 + (|y|^2 - 2 x.y); |x|^2 is hoisted out of the min.
__global__ __launch_bounds__(THREADS, 1)
void chamfer_kernel(const float* __restrict__ reg,
                    const float* __restrict__ p1) {
    __shared__ float4 sy[NPTS];       // 32 KB
    __shared__ float  sred[THREADS];

    const int blk   = blockIdx.x;
    const int dir   = blk >> 6;       // 0: x=reg,y=p1 (dist1); 1: x=p1,y=reg (dist2)
    const int rem   = blk & 63;
    const int b     = rem >> 2;
    const int chunk = rem & 3;
    const int tid   = threadIdx.x;

    const float* __restrict__ xsrc = dir ? p1 : reg;
    const float* __restrict__ ysrc = dir ? reg : p1;
    const float* xb = xsrc + (size_t)b * NPTS * 3;
    const float* yb = ysrc + (size_t)b * NPTS * 3;

    // Cooperative load of target cloud, precompute |y|^2 into .w
    for (int j = tid; j < NPTS; j += THREADS) {
        float a0 = yb[j * 3 + 0];
        float a1 = yb[j * 3 + 1];
        float a2 = yb[j * 3 + 2];
        sy[j] = make_float4(a0, a1, a2, a0 * a0 + a1 * a1 + a2 * a2);
    }
    __syncthreads();

    // This thread's 2 query points
    const int p0 = chunk * 512 + tid;
    const int p1i = p0 + 256;
    const float x0 = xb[p0 * 3 + 0], y0 = xb[p0 * 3 + 1], z0 = xb[p0 * 3 + 2];
    const float x1 = xb[p1i * 3 + 0], y1 = xb[p1i * 3 + 1], z1 = xb[p1i * 3 + 2];
    const float n0 = x0 * x0 + y0 * y0 + z0 * z0;
    const float n1 = x1 * x1 + y1 * y1 + z1 * z1;

    float m0 = 3.0e38f;
    float m1 = 3.0e38f;

    #pragma unroll 4
    for (int j = 0; j < NPTS; j++) {
        const float4 q = sy[j];                 // broadcast LDS.128
        // point 0: t = q.w - 2 * (x.q)
        float d0 = x0 * q.x;
        d0 = fmaf(y0, q.y, d0);
        d0 = fmaf(z0, q.z, d0);
        const float t0 = fmaf(-2.0f, d0, q.w);  // FFMA-imm (rt=1)
        m0 = fminf(m0, t0);
        // point 1
        float d1 = x1 * q.x;
        d1 = fmaf(y1, q.y, d1);
        d1 = fmaf(z1, q.z, d1);
        const float t1 = fmaf(-2.0f, d1, q.w);
        m1 = fminf(m1, t1);
    }

    // This thread's contribution: sum of its two min squared distances
    float s = (n0 + m0) + (n1 + m1);

    // Deterministic block tree-reduction
    sred[tid] = s;
    __syncthreads();
    #pragma unroll
    for (int off = THREADS / 2; off >= 32; off >>= 1) {
        if (tid < off) sred[tid] += sred[tid + off];
        __syncthreads();
    }
    if (tid < 32) {
        float v = sred[tid];
        #pragma unroll
        for (int off = 16; off > 0; off >>= 1)
            v += __shfl_down_sync(0xFFFFFFFFu, v, off);
        if (tid == 0) g_partials[blk] = v;
    }
}

// Single block: sum the 128 partials, add NLL, write scalar.
// Target dtype sniff: JAX with x64 disabled emits int32 despite the reference
// declaring int64. If the buffer really is int64 (little-endian, values < 40),
// every odd 32-bit word is 0; with genuine int32 random targets in [0,40) the
// chance all 8 odd words are zero is 40^-8 ~ 0. Deterministic either way.
__global__ void finalize_kernel(const float* __restrict__ pred,
                                const int* __restrict__ target32,
                                float* __restrict__ out) {
    __shared__ float sh[NBLOCKS];
    const int tid = threadIdx.x;
    sh[tid] = g_partials[tid];
    __syncthreads();
    #pragma unroll
    for (int off = NBLOCKS / 2; off >= 32; off >>= 1) {
        if (tid < off) sh[tid] += sh[tid + off];
        __syncthreads();
    }
    if (tid < 32) {
        float v = sh[tid];
        #pragma unroll
        for (int off = 16; off > 0; off >>= 1)
            v += __shfl_down_sync(0xFFFFFFFFu, v, off);
        if (tid == 0) {
            const float reg_loss = v / (float)(BATCH * NPTS);

            // dtype sniff: int64 iff all odd words of the first 16 are zero
            bool is64 = true;
            #pragma unroll
            for (int b = 0; b < 8; b++) {
                if (target32[2 * b + 1] != 0) { is64 = false; }
            }
            float nll = 0.0f;
            #pragma unroll
            for (int b = 0; b < BATCH; b++) {
                int t = is64 ? target32[2 * b] : target32[b];
                t = (t < 0) ? 0 : (t >= NUM_CLASSES ? NUM_CLASSES - 1 : t);
                nll -= pred[b * NUM_CLASSES + t];
            }
            nll /= (float)BATCH;
            out[0] = nll + reg_loss;
        }
    }
}

extern "C" void kernel_launch(void* const* d_in, const int* in_sizes, int n_in,
                              void* d_out, int out_size) {
    const float* reg    = (const float*)d_in[0];      // [16, 2048, 3]
    const float* p1     = (const float*)d_in[1];      // [16, 2048, 3]
    const float* pred   = (const float*)d_in[2];      // [16, 40] log-probs
    const int*   target = (const int*)d_in[3];        // [16] int32 (or int64, sniffed)
    float* out = (float*)d_out;

    chamfer_kernel<<<NBLOCKS, THREADS>>>(reg, p1);
    finalize_kernel<<<1, NBLOCKS>>>(pred, target, out);
}